// round 13
// baseline (speedup 1.0000x reference)
#include <cuda_runtime.h>

#define NN 50000
#define EE 800000
#define FOUTC 64
#define ASTRIDE 128   // A row: [0:32)=T1o [32:64)=T1i [64:96)=T2o [96:128)=T2i
#define SCAN_BLOCKS ((NN + 255) / 256)   // 196

typedef unsigned long long u64;

// ---- scratch (static device globals; no allocation) ----
__device__ float g_deg_out[NN];
__device__ float g_deg_in[NN];
__device__ int   g_cnt_in[NN];
__device__ int   g_tmp[NN];
__device__ int   g_M;              // #edges whose int32 key dst*N+src does NOT wrap
__device__ int   g_csc_ptr[NN + 1];
__device__ int   g_csr_ptr[NN + 1];
__device__ int   g_blk[SCAN_BLOCKS];
__device__ int   g_blkoff[SCAN_BLOCKS];
__device__ int   g_csc_edge[EE];   // bucket-scattered edge ids
__device__ float2 g_fpk[EE];       // per csc slot: {as_float(src), 1/deg_out[src]}
__device__ float2 g_rpk[EE];       // per edge id:  {as_float(dst), wrap-rotated 1/deg_in}
__device__ float g_A[(size_t)NN * ASTRIDE];
__device__ float g_Weff[2][160 * FOUTC];   // [0]=z, [1]=h ; rows = X|T1o|T1i|T2o|T2i

// ---- f32x2 packed FMA helpers (sm_103a) ----
__device__ __forceinline__ u64 pack2(float x) {
    u64 r;
    asm("mov.b64 %0, {%1, %1};" : "=l"(r) : "f"(x));
    return r;
}
__device__ __forceinline__ u64 pack2b(float x, float y) {
    u64 r;
    asm("mov.b64 %0, {%1, %2};" : "=l"(r) : "f"(x), "f"(y));
    return r;
}
__device__ __forceinline__ void fma2(u64& acc, u64 a, u64 b) {
    asm("fma.rn.f32x2 %0, %1, %2, %0;" : "+l"(acc) : "l"(a), "l"(b));
}
__device__ __forceinline__ void unpack2(float& lo, float& hi, u64 v) {
    asm("mov.b64 {%0, %1}, %2;" : "=f"(lo), "=f"(hi) : "l"(v));
}

// ---------------------------------------------------------------------------
__device__ __forceinline__ int lower_bound_src(const int* __restrict__ src, int s) {
    int lo = 0, hi = EE;
    while (lo < hi) {
        int mid = (lo + hi) >> 1;
        if (src[mid] < s) lo = mid + 1; else hi = mid;
    }
    return lo;
}

// Side-stream init: csr_ptr (binary search), deg_out (CSR gather), Weff.
__global__ void k_init(const int* __restrict__ src, const float* __restrict__ ew,
                       const float* __restrict__ Wz, const float* __restrict__ Wh) {
    int t = blockIdx.x * blockDim.x + threadIdx.x;
    if (t <= NN) {
        int lo = lower_bound_src(src, t);
        g_csr_ptr[t] = lo;
        if (t < NN) {
            int hi = lower_bound_src(src, t + 1);
            float sum = 0.f;
            for (int e = lo; e < hi; e++) sum += ew[e];
            g_deg_out[t] = sum;
        }
    }
    // Weff: W shape (2,3,96,64); only first 32 cin-rows live (H==0)
    if (t < 32 * 64) {
        int c = t >> 6, f = t & 63;
#define WI(W, s, k) W[(((s) * 3 + (k)) * 96 + c) * 64 + f]
        g_Weff[0][(0   + c) * 64 + f] = WI(Wz, 0, 0) + WI(Wz, 1, 0);  // X
        g_Weff[0][(32  + c) * 64 + f] = WI(Wz, 0, 1);                 // T1o
        g_Weff[0][(64  + c) * 64 + f] = WI(Wz, 1, 1);                 // T1i
        g_Weff[0][(96  + c) * 64 + f] = WI(Wz, 0, 2);                 // T2o
        g_Weff[0][(128 + c) * 64 + f] = WI(Wz, 1, 2);                 // T2i
        g_Weff[1][(0   + c) * 64 + f] = WI(Wh, 0, 0) + WI(Wh, 1, 0);
        g_Weff[1][(32  + c) * 64 + f] = WI(Wh, 0, 1);
        g_Weff[1][(64  + c) * 64 + f] = WI(Wh, 1, 1);
        g_Weff[1][(96  + c) * 64 + f] = WI(Wh, 0, 2);
        g_Weff[1][(128 + c) * 64 + f] = WI(Wh, 1, 2);
#undef WI
    }
}

// cnt_in histogram (atomics).
__global__ void k_degin(const int* __restrict__ dst) {
    int e = blockIdx.x * blockDim.x + threadIdx.x;
    if (e < EE) atomicAdd(&g_cnt_in[dst[e]], 1);
}

// ---- multi-block exclusive scan of cnt_in -> csc_ptr ----
__global__ void k_scan1() {
    __shared__ int sh[256];
    int tid = threadIdx.x;
    int gid = blockIdx.x * 256 + tid;
    int v = (gid < NN) ? g_cnt_in[gid] : 0;
    sh[tid] = v;
    __syncthreads();
    for (int off = 1; off < 256; off <<= 1) {
        int t = (tid >= off) ? sh[tid - off] : 0;
        __syncthreads();
        sh[tid] += t;
        __syncthreads();
    }
    if (gid < NN) g_csc_ptr[gid] = sh[tid] - v;
    if (tid == 255) g_blk[blockIdx.x] = sh[255];
}

__global__ void k_scan2() {
    __shared__ int sh[256];
    int tid = threadIdx.x;
    int v = (tid < SCAN_BLOCKS) ? g_blk[tid] : 0;
    sh[tid] = v;
    __syncthreads();
    for (int off = 1; off < 256; off <<= 1) {
        int t = (tid >= off) ? sh[tid - off] : 0;
        __syncthreads();
        sh[tid] += t;
        __syncthreads();
    }
    if (tid < SCAN_BLOCKS) g_blkoff[tid] = sh[tid] - v;
}

__global__ void k_scan3() {
    int gid = blockIdx.x * 256 + threadIdx.x;
    if (gid < NN) g_csc_ptr[gid] += g_blkoff[blockIdx.x];
    if (gid == 0) g_csc_ptr[NN] = EE;
}

// Scatter + deg_in accumulation + M-count (ballot).
// jax x64-disabled quirk: argsort key dst*N+src wraps in int32 for key >= 2^31;
// wrapped-key edges sort FIRST. M = #non-wrapping edges.
__global__ void k_scatter(const int* __restrict__ src, const int* __restrict__ dst,
                          const float* __restrict__ ew) {
    __shared__ int sM;
    if (threadIdx.x == 0) sM = 0;
    __syncthreads();
    int e = blockIdx.x * blockDim.x + threadIdx.x;
    bool nw = false;
    if (e < EE) {
        int d = dst[e];
        int pos = g_csc_ptr[d] + atomicAdd(&g_tmp[d], 1);
        g_csc_edge[pos] = e;
        atomicAdd(&g_deg_in[d], ew[e]);
        long long key = (long long)d * NN + (long long)src[e];
        nw = (key < 2147483648LL);
    }
    unsigned b = __ballot_sync(0xffffffffu, nw);
    if ((threadIdx.x & 31) == 0) atomicAdd(&sM, __popc(b));
    __syncthreads();
    if (threadIdx.x == 0) atomicAdd(&g_M, sM);
}

// Warp per dst node; rank by edge id via shfl (src order == edge-id order
// within a bucket). TRUE position q = beg + r; reference order = wrap rotation
// p = (q - M) mod E; positional quirk: w_rev[e] = 1/deg_in[src[p]].
__global__ void k_order(const int* __restrict__ src) {
    int w = (blockIdx.x * blockDim.x + threadIdx.x) >> 5;
    int lane = threadIdx.x & 31;
    if (w >= NN) return;
    int d = w;
    int beg = g_csc_ptr[d], end = g_csc_ptr[d + 1];
    int deg = end - beg;
    int M = g_M;
    for (int c0 = 0; c0 < deg; c0 += 32) {
        int i = c0 + lane;
        int e = 0x7fffffff;
        if (i < deg) e = g_csc_edge[beg + i];
        int r = 0;
        for (int c1 = 0; c1 < deg; c1 += 32) {
            int j = c1 + lane;
            int ej = (j < deg) ? g_csc_edge[beg + j] : 0x7fffffff;
            int lim = deg - c1; if (lim > 32) lim = 32;
            for (int l = 0; l < lim; l++) {
                int v = __shfl_sync(0xffffffffu, ej, l);
                if (v < e) r++;
            }
        }
        if (i < deg) {
            int p = beg + r - M;
            if (p < 0) p += EE;
            int se = src[e];
            g_rpk[e] = make_float2(__int_as_float(d), 1.0f / g_deg_in[src[p]]);
            g_fpk[beg + i] = make_float2(__int_as_float(se), 1.0f / g_deg_out[se]);
        }
    }
}

// Gather prop, one warp per (node, direction). No atomics.
// Metadata walked 2 edges at a time via 16B loads (aligned when index even).
__device__ __forceinline__ float gather_sum(const float2* __restrict__ meta,
                                            const float* __restrict__ in, int istride,
                                            int base, int beg, int end, int lane) {
    float acc = 0.f;
    int i = beg;
    if ((i & 1) && i < end) {
        float2 m = meta[i];
        acc += m.y * in[(size_t)__float_as_int(m.x) * istride + base + lane];
        i++;
    }
    #pragma unroll 2
    for (; i + 1 < end; i += 2) {
        float4 mm = *(const float4*)(meta + i);
        acc += mm.y * in[(size_t)__float_as_int(mm.x) * istride + base + lane];
        acc += mm.w * in[(size_t)__float_as_int(mm.z) * istride + base + lane];
    }
    if (i < end) {
        float2 m = meta[i];
        acc += m.y * in[(size_t)__float_as_int(m.x) * istride + base + lane];
    }
    return acc;
}

__global__ __launch_bounds__(256) void k_prop(const float* __restrict__ in, int istride,
                                              const float* __restrict__ X,
                                              int fi, int fo, int ri, int ro,
                                              float coef, int subx) {
    int w = (blockIdx.x * blockDim.x + threadIdx.x) >> 5;
    int lane = threadIdx.x & 31;
    if (w < NN) {
        int d = w;
        float acc = gather_sum(g_fpk, in, istride, fi, g_csc_ptr[d], g_csc_ptr[d + 1], lane);
        float r = coef * acc;
        if (subx) r -= X[(size_t)d * 32 + lane];
        g_A[(size_t)d * ASTRIDE + fo + lane] = r;
    } else if (w < 2 * NN) {
        int s = w - NN;
        float acc = gather_sum(g_rpk, in, istride, ri, g_csr_ptr[s], g_csr_ptr[s + 1], lane);
        float r = coef * acc;
        if (subx) r -= X[(size_t)s * 32 + lane];
        g_A[(size_t)s * ASTRIDE + ro + lane] = r;
    }
}

// Fused gate GEMM on packed f32x2: 256 threads, 1 node/thread,
// blockIdx.y = column half. Weight tile interleaved [k][g][z0 z1 h0 h1];
// one explicit float4 LDS.128 feeds both z/h FFMA2.
__global__ __launch_bounds__(256) void k_final(const float* __restrict__ X,
                                               const float* __restrict__ bz,
                                               const float* __restrict__ bh,
                                               float* __restrict__ out) {
    __shared__ float4 wzh[160 * 16];   // 40 KB
    int half = blockIdx.y;
    int tid = threadIdx.x;
    {
        const float2* z2 = (const float2*)g_Weff[0];
        const float2* h2 = (const float2*)g_Weff[1];
        for (int idx = tid; idx < 160 * 16; idx += 256) {
            int k = idx >> 4, g = idx & 15;
            float2 z = z2[k * 32 + half * 16 + g];
            float2 h = h2[k * 32 + half * 16 + g];
            wzh[idx] = make_float4(z.x, z.y, h.x, h.y);
        }
    }
    __syncthreads();

    int n = blockIdx.x * 256 + tid;
    if (n >= NN) return;
    const float4* x4 = (const float4*)(X + (size_t)n * 32);
    const float4* a4 = (const float4*)(g_A + (size_t)n * ASTRIDE);

    u64 az[16], ah[16];
    #pragma unroll
    for (int g = 0; g < 16; g++) { az[g] = 0ULL; ah[g] = 0ULL; }

    for (int k4 = 0; k4 < 40; k4++) {
        float4 av = (k4 < 8) ? x4[k4] : a4[k4 - 8];
        #pragma unroll
        for (int kk = 0; kk < 4; kk++) {
            u64 xx = pack2((&av.x)[kk]);
            const float4* wp = wzh + (k4 * 4 + kk) * 16;
            #pragma unroll
            for (int g = 0; g < 16; g++) {
                float4 wv = wp[g];                   // LDS.128 broadcast
                fma2(az[g], pack2b(wv.x, wv.y), xx);
                fma2(ah[g], pack2b(wv.z, wv.w), xx);
            }
        }
    }

    float* o = out + (size_t)n * FOUTC + half * 32;
    #pragma unroll
    for (int g = 0; g < 16; g++) {
        float zl, zh, hl, hh;
        unpack2(zl, zh, az[g]);
        unpack2(hl, hh, ah[g]);
        float gz0 = zl + bz[half * 32 + 2 * g];
        float gz1 = zh + bz[half * 32 + 2 * g + 1];
        float gh0 = hl + bh[half * 32 + 2 * g];
        float gh1 = hh + bh[half * 32 + 2 * g + 1];
        float k0 = 1.0f - 1.0f / (1.0f + __expf(-gz0));
        float k1 = 1.0f - 1.0f / (1.0f + __expf(-gz1));
        float t0 = 2.0f / (1.0f + __expf(-2.0f * gh0)) - 1.0f;
        float t1 = 2.0f / (1.0f + __expf(-2.0f * gh1)) - 1.0f;
        o[2 * g]     = k0 * t0;
        o[2 * g + 1] = k1 * t1;
    }
}

// ---------------------------------------------------------------------------
extern "C" void kernel_launch(void* const* d_in, const int* in_sizes, int n_in,
                              void* d_out, int out_size) {
    const float* X  = (const float*)d_in[0];
    const int*   ei = (const int*)d_in[1];          // [2, E] row-major
    const float* ew = (const float*)d_in[2];
    const float* Wz = (const float*)d_in[3];
    const float* bz = (const float*)d_in[4];
    // d_in[5]=Wr, d_in[6]=br dead: H==0 -> Z*H==0 and H*R==0
    const float* Wh = (const float*)d_in[7];
    const float* bh = (const float*)d_in[8];
    float* out = (float*)d_out;

    const int* src = ei;
    const int* dst = ei + EE;

    void *Ag = nullptr, *pDegIn = nullptr, *pCnt = nullptr, *pTmp = nullptr, *pM = nullptr;
    cudaGetSymbolAddress(&Ag, g_A);
    cudaGetSymbolAddress(&pDegIn, g_deg_in);
    cudaGetSymbolAddress(&pCnt, g_cnt_in);
    cudaGetSymbolAddress(&pTmp, g_tmp);
    cudaGetSymbolAddress(&pM, g_M);

    // one-time side-stream resources (handles only; no device memory)
    static cudaStream_t s2 = nullptr;
    static cudaEvent_t evFork = nullptr, evJoin = nullptr;
    if (!s2) {
        cudaStreamCreateWithFlags(&s2, cudaStreamNonBlocking);
        cudaEventCreateWithFlags(&evFork, cudaEventDisableTiming);
        cudaEventCreateWithFlags(&evJoin, cudaEventDisableTiming);
    }

    // zero the atomic targets via memset nodes
    cudaMemsetAsync(pDegIn, 0, NN * sizeof(float), 0);
    cudaMemsetAsync(pCnt, 0, NN * sizeof(int), 0);
    cudaMemsetAsync(pTmp, 0, NN * sizeof(int), 0);
    cudaMemsetAsync(pM, 0, sizeof(int), 0);

    // fork: k_init runs concurrently with the histogram/scan/scatter chain
    cudaEventRecord(evFork, 0);
    cudaStreamWaitEvent(s2, evFork, 0);
    k_init<<<(NN + 1 + 255) / 256, 256, 0, s2>>>(src, ew, Wz, Wh);
    cudaEventRecord(evJoin, s2);

    k_degin<<<(EE + 255) / 256, 256>>>(dst);
    k_scan1<<<SCAN_BLOCKS, 256>>>();
    k_scan2<<<1, 256>>>();
    k_scan3<<<SCAN_BLOCKS, 256>>>();
    k_scatter<<<(EE + 255) / 256, 256>>>(src, dst, ew);

    // join: k_order needs deg_out/csr (k_init) + csc/deg_in/M (chain)
    cudaStreamWaitEvent(0, evJoin, 0);
    k_order<<<(NN * 32 + 255) / 256, 256>>>(src);

    int prop_blocks = (2 * NN * 32 + 255) / 256;
    // T1o (A cols 0-31) = fwd(X); T1i (32-63) = rev(X)
    k_prop<<<prop_blocks, 256>>>(X, 32, X, 0, 0, 0, 32, 1.0f, 0);
    // T2o (64-95) = 2*fwd(T1o) - X; T2i (96-127) = 2*rev(T1i) - X
    k_prop<<<prop_blocks, 256>>>((const float*)Ag, ASTRIDE, X, 0, 64, 32, 96, 2.0f, 1);

    dim3 fgrid((NN + 255) / 256, 2);
    k_final<<<fgrid, 256>>>(X, bz, bh, out);
}

// round 15
// speedup vs baseline: 1.0617x; 1.0617x over previous
#include <cuda_runtime.h>

#define NN 50000
#define EE 800000
#define FOUTC 64
#define ASTRIDE 128   // A row: [0:32)=T1o [32:64)=T1i [64:96)=T2o [96:128)=T2i
#define SCAN_BLOCKS ((NN + 255) / 256)   // 196

typedef unsigned long long u64;

// ---- scratch (static device globals; no allocation) ----
__device__ float g_deg_out[NN];
__device__ float g_deg_in[NN];
__device__ int   g_cnt_in[NN];
__device__ int   g_tmp[NN];
__device__ int   g_M;              // #edges whose int32 key dst*N+src does NOT wrap
__device__ int   g_csc_ptr[NN + 1];
__device__ int   g_csr_ptr[NN + 1];
__device__ int   g_blk[SCAN_BLOCKS];
__device__ int   g_blkoff[SCAN_BLOCKS];
__device__ int   g_csc_edge[EE];   // bucket-scattered edge ids
__device__ float2 g_fpk[EE];       // per csc slot: {as_float(src), 1/deg_out[src]}
__device__ float2 g_rpk[EE];       // per edge id:  {as_float(dst), wrap-rotated 1/deg_in}
__device__ float g_A[(size_t)NN * ASTRIDE];
__device__ float g_Weff[2][160 * FOUTC];   // [0]=z, [1]=h ; rows = X|T1o|T1i|T2o|T2i

// ---- f32x2 packed FMA helpers (sm_103a) ----
__device__ __forceinline__ u64 pack2(float x) {
    u64 r;
    asm("mov.b64 %0, {%1, %1};" : "=l"(r) : "f"(x));
    return r;
}
__device__ __forceinline__ void fma2(u64& acc, u64 a, u64 b) {
    asm("fma.rn.f32x2 %0, %1, %2, %0;" : "+l"(acc) : "l"(a), "l"(b));
}
__device__ __forceinline__ void unpack2(float& lo, float& hi, u64 v) {
    asm("mov.b64 {%0, %1}, %2;" : "=f"(lo), "=f"(hi) : "l"(v));
}

// ---------------------------------------------------------------------------
__device__ __forceinline__ int lower_bound_src(const int* __restrict__ src, int s) {
    int lo = 0, hi = EE;
    while (lo < hi) {
        int mid = (lo + hi) >> 1;
        if (src[mid] < s) lo = mid + 1; else hi = mid;
    }
    return lo;
}

// Stream-0 head: zero everything the atomic chain touches.
__global__ void k_zero() {
    int i = blockIdx.x * blockDim.x + threadIdx.x;
    if (i < NN) {
        g_deg_in[i] = 0.f;
        g_cnt_in[i] = 0;
        g_tmp[i] = 0;
    }
    if (i == 0) g_M = 0;
}

// Side-stream init: csr_ptr (binary search), deg_out (CSR gather), Weff.
__global__ void k_init(const int* __restrict__ src, const float* __restrict__ ew,
                       const float* __restrict__ Wz, const float* __restrict__ Wh) {
    int t = blockIdx.x * blockDim.x + threadIdx.x;
    if (t <= NN) {
        int lo = lower_bound_src(src, t);
        g_csr_ptr[t] = lo;
        if (t < NN) {
            int hi = lower_bound_src(src, t + 1);
            float sum = 0.f;
            for (int e = lo; e < hi; e++) sum += ew[e];
            g_deg_out[t] = sum;
        }
    }
    // Weff: W shape (2,3,96,64); only first 32 cin-rows live (H==0)
    if (t < 32 * 64) {
        int c = t >> 6, f = t & 63;
#define WI(W, s, k) W[(((s) * 3 + (k)) * 96 + c) * 64 + f]
        g_Weff[0][(0   + c) * 64 + f] = WI(Wz, 0, 0) + WI(Wz, 1, 0);  // X
        g_Weff[0][(32  + c) * 64 + f] = WI(Wz, 0, 1);                 // T1o
        g_Weff[0][(64  + c) * 64 + f] = WI(Wz, 1, 1);                 // T1i
        g_Weff[0][(96  + c) * 64 + f] = WI(Wz, 0, 2);                 // T2o
        g_Weff[0][(128 + c) * 64 + f] = WI(Wz, 1, 2);                 // T2i
        g_Weff[1][(0   + c) * 64 + f] = WI(Wh, 0, 0) + WI(Wh, 1, 0);
        g_Weff[1][(32  + c) * 64 + f] = WI(Wh, 0, 1);
        g_Weff[1][(64  + c) * 64 + f] = WI(Wh, 1, 1);
        g_Weff[1][(96  + c) * 64 + f] = WI(Wh, 0, 2);
        g_Weff[1][(128 + c) * 64 + f] = WI(Wh, 1, 2);
#undef WI
    }
}

// cnt_in histogram (atomics).
__global__ void k_degin(const int* __restrict__ dst) {
    int e = blockIdx.x * blockDim.x + threadIdx.x;
    if (e < EE) atomicAdd(&g_cnt_in[dst[e]], 1);
}

// ---- multi-block exclusive scan of cnt_in -> csc_ptr ----
__global__ void k_scan1() {
    __shared__ int sh[256];
    int tid = threadIdx.x;
    int gid = blockIdx.x * 256 + tid;
    int v = (gid < NN) ? g_cnt_in[gid] : 0;
    sh[tid] = v;
    __syncthreads();
    for (int off = 1; off < 256; off <<= 1) {
        int t = (tid >= off) ? sh[tid - off] : 0;
        __syncthreads();
        sh[tid] += t;
        __syncthreads();
    }
    if (gid < NN) g_csc_ptr[gid] = sh[tid] - v;
    if (tid == 255) g_blk[blockIdx.x] = sh[255];
}

__global__ void k_scan2() {
    __shared__ int sh[256];
    int tid = threadIdx.x;
    int v = (tid < SCAN_BLOCKS) ? g_blk[tid] : 0;
    sh[tid] = v;
    __syncthreads();
    for (int off = 1; off < 256; off <<= 1) {
        int t = (tid >= off) ? sh[tid - off] : 0;
        __syncthreads();
        sh[tid] += t;
        __syncthreads();
    }
    if (tid < SCAN_BLOCKS) g_blkoff[tid] = sh[tid] - v;
}

__global__ void k_scan3() {
    int gid = blockIdx.x * 256 + threadIdx.x;
    if (gid < NN) g_csc_ptr[gid] += g_blkoff[blockIdx.x];
    if (gid == 0) g_csc_ptr[NN] = EE;
}

// Scatter + deg_in accumulation + M-count (ballot).
// jax x64-disabled quirk: argsort key dst*N+src wraps in int32 for key >= 2^31;
// wrapped-key edges sort FIRST. M = #non-wrapping edges.
__global__ void k_scatter(const int* __restrict__ src, const int* __restrict__ dst,
                          const float* __restrict__ ew) {
    __shared__ int sM;
    if (threadIdx.x == 0) sM = 0;
    __syncthreads();
    int e = blockIdx.x * blockDim.x + threadIdx.x;
    bool nw = false;
    if (e < EE) {
        int d = dst[e];
        int pos = g_csc_ptr[d] + atomicAdd(&g_tmp[d], 1);
        g_csc_edge[pos] = e;
        atomicAdd(&g_deg_in[d], ew[e]);
        long long key = (long long)d * NN + (long long)src[e];
        nw = (key < 2147483648LL);
    }
    unsigned b = __ballot_sync(0xffffffffu, nw);
    if ((threadIdx.x & 31) == 0) atomicAdd(&sM, __popc(b));
    __syncthreads();
    if (threadIdx.x == 0) atomicAdd(&g_M, sM);
}

// Warp per dst node; rank by edge id via shfl (src order == edge-id order
// within a bucket). TRUE position q = beg + r; reference order = wrap rotation
// p = (q - M) mod E; positional quirk: w_rev[e] = 1/deg_in[src[p]].
__global__ void k_order(const int* __restrict__ src) {
    int w = (blockIdx.x * blockDim.x + threadIdx.x) >> 5;
    int lane = threadIdx.x & 31;
    if (w >= NN) return;
    int d = w;
    int beg = g_csc_ptr[d], end = g_csc_ptr[d + 1];
    int deg = end - beg;
    int M = g_M;
    for (int c0 = 0; c0 < deg; c0 += 32) {
        int i = c0 + lane;
        int e = 0x7fffffff;
        if (i < deg) e = g_csc_edge[beg + i];
        int r = 0;
        for (int c1 = 0; c1 < deg; c1 += 32) {
            int j = c1 + lane;
            int ej = (j < deg) ? g_csc_edge[beg + j] : 0x7fffffff;
            int lim = deg - c1; if (lim > 32) lim = 32;
            for (int l = 0; l < lim; l++) {
                int v = __shfl_sync(0xffffffffu, ej, l);
                if (v < e) r++;
            }
        }
        if (i < deg) {
            int p = beg + r - M;
            if (p < 0) p += EE;
            int se = src[e];
            g_rpk[e] = make_float2(__int_as_float(d), 1.0f / g_deg_in[src[p]]);
            g_fpk[beg + i] = make_float2(__int_as_float(se), 1.0f / g_deg_out[se]);
        }
    }
}

// Single-direction gather prop, one warp per node (R12-proven inner loop).
// dirsel=0: fwd via csc (g_fpk);  dirsel=1: rev via csr (g_rpk).
__global__ __launch_bounds__(256) void k_prop1(const float* __restrict__ in, int istride,
                                               const float* __restrict__ X,
                                               int fi, int fo, float coef, int subx,
                                               int dirsel) {
    int w = (blockIdx.x * blockDim.x + threadIdx.x) >> 5;
    int lane = threadIdx.x & 31;
    if (w >= NN) return;
    const int* ptr = dirsel ? g_csr_ptr : g_csc_ptr;
    const float2* meta = dirsel ? g_rpk : g_fpk;
    int beg = ptr[w], end = ptr[w + 1];
    float acc = 0.f;
    #pragma unroll 4
    for (int i = beg; i < end; i++) {
        float2 m = meta[i];
        acc += m.y * in[(size_t)__float_as_int(m.x) * istride + fi + lane];
    }
    float r = coef * acc;
    if (subx) r -= X[(size_t)w * 32 + lane];
    g_A[(size_t)w * ASTRIDE + fo + lane] = r;
}

// Fused gate GEMM on packed f32x2 (R12-proven): 256 threads, 1 node/thread,
// blockIdx.y = column half. Weight tile interleaved [k][g][z0 z1 h0 h1].
__global__ __launch_bounds__(256) void k_final(const float* __restrict__ X,
                                               const float* __restrict__ bz,
                                               const float* __restrict__ bh,
                                               float* __restrict__ out) {
    __shared__ float4 wzh[160 * 16];   // 40 KB
    int half = blockIdx.y;
    int tid = threadIdx.x;
    {
        const float2* z2 = (const float2*)g_Weff[0];
        const float2* h2 = (const float2*)g_Weff[1];
        for (int idx = tid; idx < 160 * 16; idx += 256) {
            int k = idx >> 4, g = idx & 15;
            float2 z = z2[k * 32 + half * 16 + g];
            float2 h = h2[k * 32 + half * 16 + g];
            wzh[idx] = make_float4(z.x, z.y, h.x, h.y);
        }
    }
    __syncthreads();

    int n = blockIdx.x * 256 + tid;
    if (n >= NN) return;
    const float4* x4 = (const float4*)(X + (size_t)n * 32);
    const float4* a4 = (const float4*)(g_A + (size_t)n * ASTRIDE);

    u64 az[16], ah[16];
    #pragma unroll
    for (int g = 0; g < 16; g++) { az[g] = 0ULL; ah[g] = 0ULL; }

    for (int k4 = 0; k4 < 40; k4++) {
        float4 av = (k4 < 8) ? x4[k4] : a4[k4 - 8];
        #pragma unroll
        for (int kk = 0; kk < 4; kk++) {
            u64 xx = pack2((&av.x)[kk]);
            const u64* wp = (const u64*)(wzh + (k4 * 4 + kk) * 16);
            #pragma unroll
            for (int g = 0; g < 16; g++) {
                fma2(az[g], wp[2 * g], xx);
                fma2(ah[g], wp[2 * g + 1], xx);
            }
        }
    }

    float* o = out + (size_t)n * FOUTC + half * 32;
    #pragma unroll
    for (int g = 0; g < 16; g++) {
        float zl, zh, hl, hh;
        unpack2(zl, zh, az[g]);
        unpack2(hl, hh, ah[g]);
        float gz0 = zl + bz[half * 32 + 2 * g];
        float gz1 = zh + bz[half * 32 + 2 * g + 1];
        float gh0 = hl + bh[half * 32 + 2 * g];
        float gh1 = hh + bh[half * 32 + 2 * g + 1];
        float k0 = 1.0f - 1.0f / (1.0f + __expf(-gz0));
        float k1 = 1.0f - 1.0f / (1.0f + __expf(-gz1));
        float t0 = 2.0f / (1.0f + __expf(-2.0f * gh0)) - 1.0f;
        float t1 = 2.0f / (1.0f + __expf(-2.0f * gh1)) - 1.0f;
        o[2 * g]     = k0 * t0;
        o[2 * g + 1] = k1 * t1;
    }
}

// ---------------------------------------------------------------------------
extern "C" void kernel_launch(void* const* d_in, const int* in_sizes, int n_in,
                              void* d_out, int out_size) {
    const float* X  = (const float*)d_in[0];
    const int*   ei = (const int*)d_in[1];          // [2, E] row-major
    const float* ew = (const float*)d_in[2];
    const float* Wz = (const float*)d_in[3];
    const float* bz = (const float*)d_in[4];
    // d_in[5]=Wr, d_in[6]=br dead: H==0 -> Z*H==0 and H*R==0
    const float* Wh = (const float*)d_in[7];
    const float* bh = (const float*)d_in[8];
    float* out = (float*)d_out;

    const int* src = ei;
    const int* dst = ei + EE;
    const float* Ag = nullptr;
    cudaGetSymbolAddress((void**)&Ag, g_A);

    // one-time side-stream resources (handles only; no device memory)
    static cudaStream_t s2 = nullptr;
    static cudaEvent_t evFork = nullptr, evJoin = nullptr, evOrd = nullptr, evRev = nullptr;
    if (!s2) {
        cudaStreamCreateWithFlags(&s2, cudaStreamNonBlocking);
        cudaEventCreateWithFlags(&evFork, cudaEventDisableTiming);
        cudaEventCreateWithFlags(&evJoin, cudaEventDisableTiming);
        cudaEventCreateWithFlags(&evOrd, cudaEventDisableTiming);
        cudaEventCreateWithFlags(&evRev, cudaEventDisableTiming);
    }

    // fork: k_init runs concurrently with the histogram/scan/scatter chain
    k_zero<<<SCAN_BLOCKS, 256>>>();
    cudaEventRecord(evFork, 0);
    cudaStreamWaitEvent(s2, evFork, 0);
    k_init<<<(NN + 1 + 255) / 256, 256, 0, s2>>>(src, ew, Wz, Wh);
    cudaEventRecord(evJoin, s2);

    k_degin<<<(EE + 255) / 256, 256>>>(dst);
    k_scan1<<<SCAN_BLOCKS, 256>>>();
    k_scan2<<<1, 256>>>();
    k_scan3<<<SCAN_BLOCKS, 256>>>();
    k_scatter<<<(EE + 255) / 256, 256>>>(src, dst, ew);

    // join: k_order needs deg_out/csr (k_init) + csc/deg_in/M (chain)
    cudaStreamWaitEvent(0, evJoin, 0);
    k_order<<<(NN * 32 + 255) / 256, 256>>>(src);
    cudaEventRecord(evOrd, 0);

    // two independent per-direction chains, overlapped:
    int pb = (NN * 32 + 255) / 256;
    // fwd chain on stream 0: T1o (A cols 0-31) = fwd(X); T2o (64-95) = 2*fwd(T1o) - X
    k_prop1<<<pb, 256>>>(X, 32, X, 0, 0, 1.0f, 0, 0);
    k_prop1<<<pb, 256>>>(Ag, ASTRIDE, X, 0, 64, 2.0f, 1, 0);
    // rev chain on s2: T1i (32-63) = rev(X); T2i (96-127) = 2*rev(T1i) - X
    cudaStreamWaitEvent(s2, evOrd, 0);
    k_prop1<<<pb, 256, 0, s2>>>(X, 32, X, 0, 32, 1.0f, 0, 1);
    k_prop1<<<pb, 256, 0, s2>>>(Ag, ASTRIDE, X, 32, 96, 2.0f, 1, 1);
    cudaEventRecord(evRev, s2);
    cudaStreamWaitEvent(0, evRev, 0);

    dim3 fgrid((NN + 255) / 256, 2);
    k_final<<<fgrid, 256>>>(X, bz, bh, out);
}